// round 1
// baseline (speedup 1.0000x reference)
#include <cuda_runtime.h>
#include <cstdint>

#define BATCH   8
#define SEQ     4096
#define D_HID   1024
#define N_HEADS 16
#define D_HEAD  64
#define M_TOT   (BATCH * SEQ)     // 32768
#define N_TOT   (3 * D_HID)       // 3072
#define K_TOT   (D_HID)           // 1024

// Scratch (allocation-free rule: __device__ globals)
__device__ float g_qkv[(size_t)M_TOT * N_TOT];                       // 402 MB
__device__ float g_attn[(size_t)BATCH * N_HEADS * D_HEAD * D_HEAD];  // 2 MB

// ---------------------------------------------------------------------------
// K1: qkv = x @ W + b   (M=32768, N=3072, K=1024) fp32 SGEMM
// 128x128 block tile, BK=16, 256 threads, 8x8 per-thread tile (2x2 of 4x4),
// float4 smem access, A stored transposed in smem.
// ---------------------------------------------------------------------------
__global__ __launch_bounds__(256) void qkv_gemm_kernel(
    const float* __restrict__ A,      // [M, K]
    const float* __restrict__ B,      // [K, N]
    const float* __restrict__ bias)   // [N]
{
    __shared__ float As[16][128];
    __shared__ float Bs[16][128];

    const int tid = threadIdx.x;
    const int tx  = tid & 15;   // 0..15  (N direction)
    const int ty  = tid >> 4;   // 0..15  (M direction)
    const int bx  = blockIdx.x; // N tile 0..23
    const int by  = blockIdx.y; // M tile 0..255

    const float* Ab = A + (size_t)by * 128 * K_TOT;
    const float* Bb = B + (size_t)bx * 128;

    float acc[8][8];
#pragma unroll
    for (int i = 0; i < 8; i++)
#pragma unroll
        for (int j = 0; j < 8; j++) acc[i][j] = 0.f;

    for (int k0 = 0; k0 < K_TOT; k0 += 16) {
        // Load A tile 128x16 (512 float4), transpose into As[k][m]
#pragma unroll
        for (int i = 0; i < 2; i++) {
            int idx = i * 256 + tid;
            int row = idx >> 2;      // 0..127
            int c4  = idx & 3;       // 0..3
            float4 v = *(const float4*)(Ab + (size_t)row * K_TOT + k0 + c4 * 4);
            As[c4 * 4 + 0][row] = v.x;
            As[c4 * 4 + 1][row] = v.y;
            As[c4 * 4 + 2][row] = v.z;
            As[c4 * 4 + 3][row] = v.w;
        }
        // Load B tile 16x128 (512 float4)
#pragma unroll
        for (int i = 0; i < 2; i++) {
            int idx = i * 256 + tid;
            int row = idx >> 5;      // 0..15
            int c4  = idx & 31;      // 0..31
            *(float4*)(&Bs[row][c4 * 4]) =
                *(const float4*)(Bb + (size_t)(k0 + row) * N_TOT + c4 * 4);
        }
        __syncthreads();

#pragma unroll
        for (int kk = 0; kk < 16; kk++) {
            float4 a0 = *(const float4*)(&As[kk][ty * 4]);
            float4 a1 = *(const float4*)(&As[kk][64 + ty * 4]);
            float4 b0 = *(const float4*)(&Bs[kk][tx * 4]);
            float4 b1 = *(const float4*)(&Bs[kk][64 + tx * 4]);
            float a[8] = {a0.x, a0.y, a0.z, a0.w, a1.x, a1.y, a1.z, a1.w};
            float b[8] = {b0.x, b0.y, b0.z, b0.w, b1.x, b1.y, b1.z, b1.w};
#pragma unroll
            for (int i = 0; i < 8; i++)
#pragma unroll
                for (int j = 0; j < 8; j++)
                    acc[i][j] += a[i] * b[j];
        }
        __syncthreads();
    }

    // Epilogue: + bias, store to g_qkv
    float bl[8];
#pragma unroll
    for (int jb = 0; jb < 2; jb++)
#pragma unroll
        for (int jj = 0; jj < 4; jj++)
            bl[jb * 4 + jj] = bias[bx * 128 + jb * 64 + tx * 4 + jj];

    float* Cb = g_qkv + (size_t)(by * 128) * N_TOT + bx * 128;
#pragma unroll
    for (int ia = 0; ia < 2; ia++)
#pragma unroll
        for (int ii = 0; ii < 4; ii++) {
            float* crow = Cb + (size_t)(ia * 64 + ty * 4 + ii) * N_TOT;
#pragma unroll
            for (int jb = 0; jb < 2; jb++) {
                float4 r;
                r.x = acc[ia * 4 + ii][jb * 4 + 0] + bl[jb * 4 + 0];
                r.y = acc[ia * 4 + ii][jb * 4 + 1] + bl[jb * 4 + 1];
                r.z = acc[ia * 4 + ii][jb * 4 + 2] + bl[jb * 4 + 2];
                r.w = acc[ia * 4 + ii][jb * 4 + 3] + bl[jb * 4 + 3];
                *(float4*)(crow + jb * 64 + tx * 4) = r;
            }
        }
}

// ---------------------------------------------------------------------------
// K2: per (b,h): S[d,e] = sum_n q[n,d]*k[n,e] / 8; attn = softmax_e(S)
// 1 block per (b,h), 256 threads = 4 groups x 64, each group handles 1/4 of n.
// Thread tile: 4d x 16e. Group partials reduced in smem, then softmax.
// ---------------------------------------------------------------------------
__global__ __launch_bounds__(256) void attn_softmax_kernel()
{
    __shared__ float pool[2 * 64 * 64];   // qs | ks during mainloop; S overlay at end
    float* qs = pool;
    float* ks = pool + 4096;

    const int tid = threadIdx.x;
    const int bh  = blockIdx.x;           // 0..127
    const int b   = bh >> 4, h = bh & 15;

    const float* qb = g_qkv + (size_t)b * SEQ * N_TOT + h * 64;
    const float* kb = qb + D_HID;

    const int grp = tid >> 6;             // 0..3 (n-split group)
    const int s   = tid & 63;
    const int d0  = (s >> 2) * 4;         // 0,4,...,60
    const int e0  = (s & 3) * 16;         // 0,16,32,48

    float acc[4][16];
#pragma unroll
    for (int i = 0; i < 4; i++)
#pragma unroll
        for (int j = 0; j < 16; j++) acc[i][j] = 0.f;

    for (int c = 0; c < 64; c++) {
        const int n0 = c * 64;
        // cooperative load of 64x64 q and k chunk
#pragma unroll
        for (int i = 0; i < 4; i++) {
            int idx = i * 256 + tid;      // 0..1023 float4 slots
            int row = idx >> 4;           // 0..63
            int c4  = idx & 15;           // 0..15
            *(float4*)(qs + row * 64 + c4 * 4) =
                *(const float4*)(qb + (size_t)(n0 + row) * N_TOT + c4 * 4);
            *(float4*)(ks + row * 64 + c4 * 4) =
                *(const float4*)(kb + (size_t)(n0 + row) * N_TOT + c4 * 4);
        }
        __syncthreads();

        const int nbase = grp * 16;
#pragma unroll 4
        for (int nn = 0; nn < 16; nn++) {
            const int n = nbase + nn;
            float4 qv = *(const float4*)(qs + n * 64 + d0);
            float qa[4] = {qv.x, qv.y, qv.z, qv.w};
            float kq[16];
#pragma unroll
            for (int j4 = 0; j4 < 4; j4++) {
                float4 kv = *(const float4*)(ks + n * 64 + e0 + j4 * 4);
                kq[j4 * 4 + 0] = kv.x; kq[j4 * 4 + 1] = kv.y;
                kq[j4 * 4 + 2] = kv.z; kq[j4 * 4 + 3] = kv.w;
            }
#pragma unroll
            for (int i = 0; i < 4; i++)
#pragma unroll
                for (int j = 0; j < 16; j++)
                    acc[i][j] += qa[i] * kq[j];
        }
        __syncthreads();
    }

    // Reduce group partials into S (overlay on pool), scale by 1/sqrt(64)
    float* S    = pool;                    // [64][68] padded
    float* mrow = pool + 64 * 68;          // [64]
    float* irow = mrow + 64;               // [64]
    const float scale = 0.125f;

    for (int g = 0; g < 4; g++) {
        if (grp == g) {
#pragma unroll
            for (int i = 0; i < 4; i++)
#pragma unroll
                for (int j = 0; j < 16; j++) {
                    float v = acc[i][j] * scale;
                    if (g == 0) S[(d0 + i) * 68 + e0 + j]  = v;
                    else        S[(d0 + i) * 68 + e0 + j] += v;
                }
        }
        __syncthreads();
    }

    if (tid < 64) {
        float m = -3.4e38f;
#pragma unroll
        for (int e = 0; e < 64; e++) m = fmaxf(m, S[tid * 68 + e]);
        float sum = 0.f;
#pragma unroll
        for (int e = 0; e < 64; e++) sum += __expf(S[tid * 68 + e] - m);
        mrow[tid] = m;
        irow[tid] = 1.f / sum;
    }
    __syncthreads();

    float* ag = g_attn + (size_t)bh * 4096;
#pragma unroll
    for (int i = 0; i < 16; i++) {
        int flat = i * 256 + tid;
        int d = flat >> 6, e = flat & 63;
        ag[flat] = __expf(S[d * 68 + e] - mrow[d]) * irow[d];
    }
}

// ---------------------------------------------------------------------------
// K3: out[n,e] = sum_d v[n,d] * attn[d,e], per (b,h).
// Block: 64 n-rows x 64 e, 256 threads = 4 groups split over d (16 each),
// thread tile 4n x 16e, serialized smem reduction, coalesced output.
// ---------------------------------------------------------------------------
__global__ __launch_bounds__(256) void out_gemm_kernel(float* __restrict__ out)
{
    __shared__ float vst[64 * 64];   // v transposed: vst[d][n]; reused as O[64][64]
    __shared__ float at[64 * 64];    // attn[d][e]

    const int tid = threadIdx.x;
    const int bh  = blockIdx.y;             // 0..127
    const int b   = bh >> 4, h = bh & 15;
    const int n0  = blockIdx.x * 64;        // 0..4032

    // load attn (flat, coalesced)
    const float* ag = g_attn + (size_t)bh * 4096;
#pragma unroll
    for (int i = 0; i < 4; i++) {
        int idx = i * 256 + tid;
        *(float4*)(at + idx * 4) = *(const float4*)(ag + idx * 4);
    }
    // load v chunk [64n][64d], store transposed vst[d][n]
    const float* vb = g_qkv + ((size_t)b * SEQ + n0) * N_TOT + 2 * D_HID + h * 64;
#pragma unroll
    for (int i = 0; i < 4; i++) {
        int idx = i * 256 + tid;
        int row = idx >> 4;       // n within chunk
        int c4  = idx & 15;       // d/4
        float4 v = *(const float4*)(vb + (size_t)row * N_TOT + c4 * 4);
        vst[(c4 * 4 + 0) * 64 + row] = v.x;
        vst[(c4 * 4 + 1) * 64 + row] = v.y;
        vst[(c4 * 4 + 2) * 64 + row] = v.z;
        vst[(c4 * 4 + 3) * 64 + row] = v.w;
    }
    __syncthreads();

    const int grp = tid >> 6;           // d-split group 0..3
    const int s   = tid & 63;
    const int nt0 = (s >> 2) * 4;       // 4 n-rows
    const int e0  = (s & 3) * 16;       // 16 e-cols

    float acc[4][16];
#pragma unroll
    for (int i = 0; i < 4; i++)
#pragma unroll
        for (int j = 0; j < 16; j++) acc[i][j] = 0.f;

#pragma unroll 4
    for (int dd = 0; dd < 16; dd++) {
        const int d = grp * 16 + dd;
        float4 vv = *(const float4*)(vst + d * 64 + nt0);
        float va[4] = {vv.x, vv.y, vv.z, vv.w};
        float aa[16];
#pragma unroll
        for (int j4 = 0; j4 < 4; j4++) {
            float4 av = *(const float4*)(at + d * 64 + e0 + j4 * 4);
            aa[j4 * 4 + 0] = av.x; aa[j4 * 4 + 1] = av.y;
            aa[j4 * 4 + 2] = av.z; aa[j4 * 4 + 3] = av.w;
        }
#pragma unroll
        for (int i = 0; i < 4; i++)
#pragma unroll
            for (int j = 0; j < 16; j++)
                acc[i][j] += va[i] * aa[j];
    }
    __syncthreads();   // done reading vst; reuse as O

    float* O = vst;    // [64][64]
    for (int g = 0; g < 4; g++) {
        if (grp == g) {
#pragma unroll
            for (int i = 0; i < 4; i++)
#pragma unroll
                for (int j = 0; j < 16; j++) {
                    if (g == 0) O[(nt0 + i) * 64 + e0 + j]  = acc[i][j];
                    else        O[(nt0 + i) * 64 + e0 + j] += acc[i][j];
                }
        }
        __syncthreads();
    }

    // coalesced write: out[b, n0+n, h*64 + e]
#pragma unroll
    for (int i = 0; i < 4; i++) {
        int idx = i * 256 + tid;        // 0..1023 float4 slots
        int n = idx >> 4;               // 0..63
        int c4 = idx & 15;
        float* orow = out + ((size_t)b * SEQ + n0 + n) * D_HID + h * 64;
        *(float4*)(orow + c4 * 4) = *(const float4*)(O + n * 64 + c4 * 4);
    }
}

// ---------------------------------------------------------------------------
extern "C" void kernel_launch(void* const* d_in, const int* in_sizes, int n_in,
                              void* d_out, int out_size)
{
    const float* x    = (const float*)d_in[0];   // [8,4096,1024]
    const float* W    = (const float*)d_in[1];   // [1024,3072]
    const float* bias = (const float*)d_in[2];   // [3072]
    float* out = (float*)d_out;                  // [8,4096,1024]

    dim3 g1(N_TOT / 128, M_TOT / 128);           // 24 x 256
    qkv_gemm_kernel<<<g1, 256>>>(x, W, bias);

    attn_softmax_kernel<<<BATCH * N_HEADS, 256>>>();

    dim3 g3(SEQ / 64, BATCH * N_HEADS);          // 64 x 128
    out_gemm_kernel<<<g3, 256>>>(out);
}

// round 3
// speedup vs baseline: 2.0456x; 2.0456x over previous
#include <cuda_runtime.h>
#include <cuda_bf16.h>
#include <cstdint>

#define BATCH   8
#define SEQ     4096
#define D_HID   1024
#define N_HEADS 16
#define D_HEAD  64
#define M_TOT   (BATCH * SEQ)     // 32768
#define N_TOT   (3 * D_HID)       // 3072
#define K_TOT   (D_HID)           // 1024

// Scratch (allocation-free rule: __device__ globals)
__device__ float g_qkv[(size_t)M_TOT * N_TOT];                       // 402 MB
__device__ float g_attn[(size_t)BATCH * N_HEADS * D_HEAD * D_HEAD];  // 2 MB
__device__ __nv_bfloat16 g_xh[(size_t)M_TOT * K_TOT];                // 67 MB
__device__ __nv_bfloat16 g_xl[(size_t)M_TOT * K_TOT];                // 67 MB
__device__ __nv_bfloat16 g_wth[(size_t)N_TOT * K_TOT];               // 6 MB (W^T hi)
__device__ __nv_bfloat16 g_wtl[(size_t)N_TOT * K_TOT];               // 6 MB (W^T lo)

// ---------------------------------------------------------------------------
// helpers (sm_80-era PTX only: valid at compute_103 virtual target)
// ---------------------------------------------------------------------------
__device__ __forceinline__ uint32_t smem_u32(const void* p) {
    uint32_t a;
    asm("{ .reg .u64 t; cvta.to.shared.u64 t, %1; cvt.u32.u64 %0, t; }" : "=r"(a) : "l"(p));
    return a;
}
__device__ __forceinline__ void cp16(uint32_t smem_dst, const void* gsrc) {
    asm volatile("cp.async.cg.shared.global [%0], [%1], 16;" :: "r"(smem_dst), "l"(gsrc));
}
__device__ __forceinline__ void cp_commit() {
    asm volatile("cp.async.commit_group;" ::: "memory");
}
__device__ __forceinline__ void ldsm4(uint32_t* r, uint32_t addr) {
    asm volatile("ldmatrix.sync.aligned.m8n8.x4.shared.b16 {%0,%1,%2,%3}, [%4];"
                 : "=r"(r[0]), "=r"(r[1]), "=r"(r[2]), "=r"(r[3]) : "r"(addr));
}
__device__ __forceinline__ void mma16816(float* c, const uint32_t* a, const uint32_t* b) {
    asm volatile("mma.sync.aligned.m16n8k16.row.col.f32.bf16.bf16.f32 "
                 "{%0,%1,%2,%3}, {%4,%5,%6,%7}, {%8,%9}, {%0,%1,%2,%3};"
                 : "+f"(c[0]), "+f"(c[1]), "+f"(c[2]), "+f"(c[3])
                 : "r"(a[0]), "r"(a[1]), "r"(a[2]), "r"(a[3]), "r"(b[0]), "r"(b[1]));
}

// ---------------------------------------------------------------------------
// Conversion kernels (fp32 -> bf16 hi/lo split)
// ---------------------------------------------------------------------------
__global__ __launch_bounds__(256) void convert_x_kernel(const float* __restrict__ x)
{
    size_t i = ((size_t)blockIdx.x * 256 + threadIdx.x) * 8;
    float4 a = *(const float4*)(x + i);
    float4 b = *(const float4*)(x + i + 4);
    float v[8] = {a.x, a.y, a.z, a.w, b.x, b.y, b.z, b.w};
    __nv_bfloat16 hi[8], lo[8];
#pragma unroll
    for (int j = 0; j < 8; j++) {
        hi[j] = __float2bfloat16(v[j]);
        lo[j] = __float2bfloat16(v[j] - __bfloat162float(hi[j]));
    }
    *(uint4*)(g_xh + i) = *(uint4*)hi;
    *(uint4*)(g_xl + i) = *(uint4*)lo;
}

// W [1024, 3072] fp32 -> Wt [3072, 1024] bf16 hi/lo (transpose)
__global__ __launch_bounds__(256) void convert_w_kernel(const float* __restrict__ W)
{
    __shared__ float t[32][33];
    int x0 = blockIdx.x * 32;   // n
    int y0 = blockIdx.y * 32;   // k
    int tx = threadIdx.x, ty = threadIdx.y;
#pragma unroll
    for (int j = 0; j < 4; j++)
        t[ty + j * 8][tx] = W[(size_t)(y0 + ty + j * 8) * N_TOT + x0 + tx];
    __syncthreads();
#pragma unroll
    for (int j = 0; j < 4; j++) {
        int n = x0 + ty + j * 8;
        int k = y0 + tx;
        float v = t[tx][ty + j * 8];
        __nv_bfloat16 hi = __float2bfloat16(v);
        __nv_bfloat16 lo = __float2bfloat16(v - __bfloat162float(hi));
        g_wth[(size_t)n * K_TOT + k] = hi;
        g_wtl[(size_t)n * K_TOT + k] = lo;
    }
}

// ---------------------------------------------------------------------------
// K1: qkv = x @ W + b via mma.sync bf16 3-term split GEMM
// Block 128x128, BK=64, 8 warps (warp tile 32x64), 3-stage cp.async pipeline.
// K'=3072 packed as [Ahi|Ahi|Alo] x [Bhi|Blo|Bhi] via pointer selection.
// ---------------------------------------------------------------------------
#define BM 128
#define BN 128
#define BK 64
#define NCHUNK 48
#define STAGE_BYTES 32768              // A 16KB + B 16KB
#define A_OFF(s) ((s) * STAGE_BYTES)
#define B_OFF(s) ((s) * STAGE_BYTES + 16384)
#define GEMM_SMEM (3 * STAGE_BYTES)    // 96 KB

__device__ __forceinline__ void load_chunk(uint32_t sb, int tid, int by, int bx, int c, int s)
{
    int seg  = c >> 4;           // 0: hi*hi, 1: hi*lo, 2: lo*hi
    int koff = (c & 15) * BK;
    const __nv_bfloat16* A = (seg == 2 ? g_xl : g_xh) + (size_t)(by * BM) * K_TOT + koff;
    const __nv_bfloat16* B = (seg == 1 ? g_wtl : g_wth) + (size_t)(bx * BN) * K_TOT + koff;
    uint32_t ab = sb + A_OFF(s), bb = sb + B_OFF(s);
#pragma unroll
    for (int i = 0; i < 4; i++) {
        int slot = i * 256 + tid;     // 0..1023
        int r   = slot >> 3;          // 0..127
        int c16 = slot & 7;           // 16B chunk in row
        uint32_t off = (uint32_t)(r * 128 + ((c16 ^ (r & 7)) * 16));
        cp16(ab + off, A + (size_t)r * K_TOT + c16 * 8);
        cp16(bb + off, B + (size_t)r * K_TOT + c16 * 8);
    }
}

__global__ __launch_bounds__(256) void qkv_mma_kernel(const float* __restrict__ bias)
{
    extern __shared__ __align__(128) uint8_t smem[];
    uint32_t sb = smem_u32(smem);
    const int tid  = threadIdx.x;
    const int wid  = tid >> 5;
    const int lane = tid & 31;
    const int bx = blockIdx.x;    // N tile 0..23
    const int by = blockIdx.y;    // M tile 0..255
    const int wm = wid >> 1;      // 0..3  (M dir)
    const int wn = wid & 1;       // 0..1  (N dir)

    float acc[2][8][4];
#pragma unroll
    for (int mt = 0; mt < 2; mt++)
#pragma unroll
        for (int nt = 0; nt < 8; nt++)
#pragma unroll
            for (int j = 0; j < 4; j++) acc[mt][nt][j] = 0.f;

    load_chunk(sb, tid, by, bx, 0, 0); cp_commit();
    load_chunk(sb, tid, by, bx, 1, 1); cp_commit();

    // ldmatrix lane addressing (stage-relative row / k-chunk-half)
    const int a_r = wm * 32 + (lane & 15);        // + mt*16
    const int a_h = lane >> 4;                    // k half-chunk
    const int b_r = wn * 64 + ((lane >> 4) << 3) + (lane & 7);  // + np*16
    const int b_h = (lane >> 3) & 1;

    for (int ch = 0; ch < NCHUNK; ch++) {
        const int s = ch % 3;
        asm volatile("cp.async.wait_group 1;" ::: "memory");
        __syncthreads();
        if (ch + 2 < NCHUNK) load_chunk(sb, tid, by, bx, ch + 2, (ch + 2) % 3);
        cp_commit();   // always commit (empty groups keep wait_group accounting)

        const uint32_t abase = sb + A_OFF(s);
        const uint32_t bbase = sb + B_OFF(s);
#pragma unroll
        for (int ks = 0; ks < 4; ks++) {
            uint32_t a[2][4];
#pragma unroll
            for (int mt = 0; mt < 2; mt++) {
                int r   = a_r + mt * 16;
                int c16 = ks * 2 + a_h;
                ldsm4(a[mt], abase + r * 128 + ((c16 ^ (r & 7)) * 16));
            }
            uint32_t b[8][2];
#pragma unroll
            for (int np = 0; np < 4; np++) {
                int r   = b_r + np * 16;
                int c16 = ks * 2 + b_h;
                uint32_t q[4];
                ldsm4(q, bbase + r * 128 + ((c16 ^ (r & 7)) * 16));
                b[np * 2 + 0][0] = q[0]; b[np * 2 + 0][1] = q[1];
                b[np * 2 + 1][0] = q[2]; b[np * 2 + 1][1] = q[3];
            }
#pragma unroll
            for (int mt = 0; mt < 2; mt++)
#pragma unroll
                for (int nt = 0; nt < 8; nt++)
                    mma16816(acc[mt][nt], a[mt], b[nt]);
        }
    }
    asm volatile("cp.async.wait_group 0;" ::: "memory");

    // Epilogue: acc -> g_qkv (+bias). Thread holds rows (lane>>2)+{0,8}, cols (lane&3)*2+{0,1}
    const int ncol0 = bx * BN + wn * 64 + (lane & 3) * 2;
    float b0[8], b1[8];
#pragma unroll
    for (int nt = 0; nt < 8; nt++) {
        b0[nt] = __ldg(bias + ncol0 + nt * 8);
        b1[nt] = __ldg(bias + ncol0 + nt * 8 + 1);
    }
#pragma unroll
    for (int mt = 0; mt < 2; mt++)
#pragma unroll
        for (int half = 0; half < 2; half++) {
            int m = by * BM + wm * 32 + mt * 16 + (lane >> 2) + half * 8;
            float* row = g_qkv + (size_t)m * N_TOT + ncol0;
#pragma unroll
            for (int nt = 0; nt < 8; nt++) {
                float2 v;
                v.x = acc[mt][nt][half * 2 + 0] + b0[nt];
                v.y = acc[mt][nt][half * 2 + 1] + b1[nt];
                *(float2*)(row + nt * 8) = v;
            }
        }
}

// ---------------------------------------------------------------------------
// K2: per (b,h): S[d,e] = sum_n q[n,d]*k[n,e] / 8; attn = softmax_e(S)
// ---------------------------------------------------------------------------
__global__ __launch_bounds__(256) void attn_softmax_kernel()
{
    __shared__ float pool[2 * 64 * 64];
    float* qs = pool;
    float* ks = pool + 4096;

    const int tid = threadIdx.x;
    const int bh  = blockIdx.x;
    const int b   = bh >> 4, h = bh & 15;

    const float* qb = g_qkv + (size_t)b * SEQ * N_TOT + h * 64;
    const float* kb = qb + D_HID;

    const int grp = tid >> 6;
    const int s   = tid & 63;
    const int d0  = (s >> 2) * 4;
    const int e0  = (s & 3) * 16;

    float acc[4][16];
#pragma unroll
    for (int i = 0; i < 4; i++)
#pragma unroll
        for (int j = 0; j < 16; j++) acc[i][j] = 0.f;

    for (int c = 0; c < 64; c++) {
        const int n0 = c * 64;
#pragma unroll
        for (int i = 0; i < 4; i++) {
            int idx = i * 256 + tid;
            int row = idx >> 4;
            int c4  = idx & 15;
            *(float4*)(qs + row * 64 + c4 * 4) =
                *(const float4*)(qb + (size_t)(n0 + row) * N_TOT + c4 * 4);
            *(float4*)(ks + row * 64 + c4 * 4) =
                *(const float4*)(kb + (size_t)(n0 + row) * N_TOT + c4 * 4);
        }
        __syncthreads();

        const int nbase = grp * 16;
#pragma unroll 4
        for (int nn = 0; nn < 16; nn++) {
            const int n = nbase + nn;
            float4 qv = *(const float4*)(qs + n * 64 + d0);
            float qa[4] = {qv.x, qv.y, qv.z, qv.w};
            float kq[16];
#pragma unroll
            for (int j4 = 0; j4 < 4; j4++) {
                float4 kv = *(const float4*)(ks + n * 64 + e0 + j4 * 4);
                kq[j4 * 4 + 0] = kv.x; kq[j4 * 4 + 1] = kv.y;
                kq[j4 * 4 + 2] = kv.z; kq[j4 * 4 + 3] = kv.w;
            }
#pragma unroll
            for (int i = 0; i < 4; i++)
#pragma unroll
                for (int j = 0; j < 16; j++)
                    acc[i][j] += qa[i] * kq[j];
        }
        __syncthreads();
    }

    float* S    = pool;
    float* mrow = pool + 64 * 68;
    float* irow = mrow + 64;
    const float scale = 0.125f;

    for (int g = 0; g < 4; g++) {
        if (grp == g) {
#pragma unroll
            for (int i = 0; i < 4; i++)
#pragma unroll
                for (int j = 0; j < 16; j++) {
                    float v = acc[i][j] * scale;
                    if (g == 0) S[(d0 + i) * 68 + e0 + j]  = v;
                    else        S[(d0 + i) * 68 + e0 + j] += v;
                }
        }
        __syncthreads();
    }

    if (tid < 64) {
        float m = -3.4e38f;
#pragma unroll
        for (int e = 0; e < 64; e++) m = fmaxf(m, S[tid * 68 + e]);
        float sum = 0.f;
#pragma unroll
        for (int e = 0; e < 64; e++) sum += __expf(S[tid * 68 + e] - m);
        mrow[tid] = m;
        irow[tid] = 1.f / sum;
    }
    __syncthreads();

    float* ag = g_attn + (size_t)bh * 4096;
#pragma unroll
    for (int i = 0; i < 16; i++) {
        int flat = i * 256 + tid;
        int d = flat >> 6, e = flat & 63;
        ag[flat] = __expf(S[d * 68 + e] - mrow[d]) * irow[d];
    }
}

// ---------------------------------------------------------------------------
// K3: out[n,e] = sum_d v[n,d] * attn[d,e], per (b,h)
// ---------------------------------------------------------------------------
__global__ __launch_bounds__(256) void out_gemm_kernel(float* __restrict__ out)
{
    __shared__ float vst[64 * 64];
    __shared__ float at[64 * 64];

    const int tid = threadIdx.x;
    const int bh  = blockIdx.y;
    const int b   = bh >> 4, h = bh & 15;
    const int n0  = blockIdx.x * 64;

    const float* ag = g_attn + (size_t)bh * 4096;
#pragma unroll
    for (int i = 0; i < 4; i++) {
        int idx = i * 256 + tid;
        *(float4*)(at + idx * 4) = *(const float4*)(ag + idx * 4);
    }
    const float* vb = g_qkv + ((size_t)b * SEQ + n0) * N_TOT + 2 * D_HID + h * 64;
#pragma unroll
    for (int i = 0; i < 4; i++) {
        int idx = i * 256 + tid;
        int row = idx >> 4;
        int c4  = idx & 15;
        float4 v = *(const float4*)(vb + (size_t)row * N_TOT + c4 * 4);
        vst[(c4 * 4 + 0) * 64 + row] = v.x;
        vst[(c4 * 4 + 1) * 64 + row] = v.y;
        vst[(c4 * 4 + 2) * 64 + row] = v.z;
        vst[(c4 * 4 + 3) * 64 + row] = v.w;
    }
    __syncthreads();

    const int grp = tid >> 6;
    const int s   = tid & 63;
    const int nt0 = (s >> 2) * 4;
    const int e0  = (s & 3) * 16;

    float acc[4][16];
#pragma unroll
    for (int i = 0; i < 4; i++)
#pragma unroll
        for (int j = 0; j < 16; j++) acc[i][j] = 0.f;

#pragma unroll 4
    for (int dd = 0; dd < 16; dd++) {
        const int d = grp * 16 + dd;
        float4 vv = *(const float4*)(vst + d * 64 + nt0);
        float va[4] = {vv.x, vv.y, vv.z, vv.w};
        float aa[16];
#pragma unroll
        for (int j4 = 0; j4 < 4; j4++) {
            float4 av = *(const float4*)(at + d * 64 + e0 + j4 * 4);
            aa[j4 * 4 + 0] = av.x; aa[j4 * 4 + 1] = av.y;
            aa[j4 * 4 + 2] = av.z; aa[j4 * 4 + 3] = av.w;
        }
#pragma unroll
        for (int i = 0; i < 4; i++)
#pragma unroll
            for (int j = 0; j < 16; j++)
                acc[i][j] += va[i] * aa[j];
    }
    __syncthreads();

    float* O = vst;
    for (int g = 0; g < 4; g++) {
        if (grp == g) {
#pragma unroll
            for (int i = 0; i < 4; i++)
#pragma unroll
                for (int j = 0; j < 16; j++) {
                    if (g == 0) O[(nt0 + i) * 64 + e0 + j]  = acc[i][j];
                    else        O[(nt0 + i) * 64 + e0 + j] += acc[i][j];
                }
        }
        __syncthreads();
    }

#pragma unroll
    for (int i = 0; i < 4; i++) {
        int idx = i * 256 + tid;
        int n = idx >> 4;
        int c4 = idx & 15;
        float* orow = out + ((size_t)b * SEQ + n0 + n) * D_HID + h * 64;
        *(float4*)(orow + c4 * 4) = *(const float4*)(O + n * 64 + c4 * 4);
    }
}

// ---------------------------------------------------------------------------
extern "C" void kernel_launch(void* const* d_in, const int* in_sizes, int n_in,
                              void* d_out, int out_size)
{
    const float* x    = (const float*)d_in[0];   // [8,4096,1024]
    const float* W    = (const float*)d_in[1];   // [1024,3072]
    const float* bias = (const float*)d_in[2];   // [3072]
    float* out = (float*)d_out;                  // [8,4096,1024]

    convert_x_kernel<<<(M_TOT * K_TOT) / (256 * 8), 256>>>(x);
    convert_w_kernel<<<dim3(N_TOT / 32, K_TOT / 32), dim3(32, 8)>>>(W);

    cudaFuncSetAttribute(qkv_mma_kernel, cudaFuncAttributeMaxDynamicSharedMemorySize, GEMM_SMEM);
    qkv_mma_kernel<<<dim3(N_TOT / BN, M_TOT / BM), 256, GEMM_SMEM>>>(bias);

    attn_softmax_kernel<<<BATCH * N_HEADS, 256>>>();

    dim3 g3(SEQ / 64, BATCH * N_HEADS);
    out_gemm_kernel<<<g3, 256>>>(out);
}

// round 4
// speedup vs baseline: 2.4726x; 1.2087x over previous
#include <cuda_runtime.h>
#include <cuda_bf16.h>
#include <cstdint>

#define BATCH   8
#define SEQ     4096
#define D_HID   1024
#define N_HEADS 16
#define D_HEAD  64
#define M_TOT   (BATCH * SEQ)     // 32768
#define N_TOT   (3 * D_HID)       // 3072
#define K_TOT   (D_HID)           // 1024

// Scratch (allocation-free rule: __device__ globals)
__device__ float g_qkv[(size_t)M_TOT * N_TOT];                       // 402 MB
__device__ float g_attn[(size_t)BATCH * N_HEADS * D_HEAD * D_HEAD];  // 2 MB
__device__ float g_part[(size_t)8 * 128 * 4096];                     // 16.8 MB
__device__ __nv_bfloat16 g_xh[(size_t)M_TOT * K_TOT];
__device__ __nv_bfloat16 g_xl[(size_t)M_TOT * K_TOT];
__device__ __nv_bfloat16 g_wth[(size_t)N_TOT * K_TOT];
__device__ __nv_bfloat16 g_wtl[(size_t)N_TOT * K_TOT];

// ---------------------------------------------------------------------------
// helpers
// ---------------------------------------------------------------------------
__device__ __forceinline__ uint32_t smem_u32(const void* p) {
    uint32_t a;
    asm("{ .reg .u64 t; cvta.to.shared.u64 t, %1; cvt.u32.u64 %0, t; }" : "=r"(a) : "l"(p));
    return a;
}
__device__ __forceinline__ void cp16(uint32_t smem_dst, const void* gsrc) {
    asm volatile("cp.async.cg.shared.global [%0], [%1], 16;" :: "r"(smem_dst), "l"(gsrc));
}
__device__ __forceinline__ void cp_commit() {
    asm volatile("cp.async.commit_group;" ::: "memory");
}
__device__ __forceinline__ void ldsm4(uint32_t* r, uint32_t addr) {
    asm volatile("ldmatrix.sync.aligned.m8n8.x4.shared.b16 {%0,%1,%2,%3}, [%4];"
                 : "=r"(r[0]), "=r"(r[1]), "=r"(r[2]), "=r"(r[3]) : "r"(addr));
}
__device__ __forceinline__ void mma16816(float* c, const uint32_t* a, const uint32_t* b) {
    asm volatile("mma.sync.aligned.m16n8k16.row.col.f32.bf16.bf16.f32 "
                 "{%0,%1,%2,%3}, {%4,%5,%6,%7}, {%8,%9}, {%0,%1,%2,%3};"
                 : "+f"(c[0]), "+f"(c[1]), "+f"(c[2]), "+f"(c[3])
                 : "r"(a[0]), "r"(a[1]), "r"(a[2]), "r"(a[3]), "r"(b[0]), "r"(b[1]));
}
// packed fp32x2 FMA (sm_100-family base ISA)
#define FMA2(acc64, a64, b64) \
    asm("fma.rn.f32x2 %0, %1, %2, %0;" : "+l"(acc64) : "l"(a64), "l"(b64))
#define PACK2(dst, lo, hi) \
    asm("mov.b64 %0, {%1, %2};" : "=l"(dst) : "f"(lo), "f"(hi))

// ---------------------------------------------------------------------------
// Conversion kernels (fp32 -> bf16 hi/lo split)
// ---------------------------------------------------------------------------
__global__ __launch_bounds__(256) void convert_x_kernel(const float* __restrict__ x)
{
    size_t i = ((size_t)blockIdx.x * 256 + threadIdx.x) * 8;
    float4 a = *(const float4*)(x + i);
    float4 b = *(const float4*)(x + i + 4);
    float v[8] = {a.x, a.y, a.z, a.w, b.x, b.y, b.z, b.w};
    __nv_bfloat16 hi[8], lo[8];
#pragma unroll
    for (int j = 0; j < 8; j++) {
        hi[j] = __float2bfloat16(v[j]);
        lo[j] = __float2bfloat16(v[j] - __bfloat162float(hi[j]));
    }
    *(uint4*)(g_xh + i) = *(uint4*)hi;
    *(uint4*)(g_xl + i) = *(uint4*)lo;
}

__global__ __launch_bounds__(256) void convert_w_kernel(const float* __restrict__ W)
{
    __shared__ float t[32][33];
    int x0 = blockIdx.x * 32;   // n
    int y0 = blockIdx.y * 32;   // k
    int tx = threadIdx.x, ty = threadIdx.y;
#pragma unroll
    for (int j = 0; j < 4; j++)
        t[ty + j * 8][tx] = W[(size_t)(y0 + ty + j * 8) * N_TOT + x0 + tx];
    __syncthreads();
#pragma unroll
    for (int j = 0; j < 4; j++) {
        int n = x0 + ty + j * 8;
        int k = y0 + tx;
        float v = t[tx][ty + j * 8];
        __nv_bfloat16 hi = __float2bfloat16(v);
        __nv_bfloat16 lo = __float2bfloat16(v - __bfloat162float(hi));
        g_wth[(size_t)n * K_TOT + k] = hi;
        g_wtl[(size_t)n * K_TOT + k] = lo;
    }
}

// ---------------------------------------------------------------------------
// K1: qkv = x @ W + b via mma.sync bf16 3-term split GEMM
// Block 256x128, BK=64, 16 warps (warp tile 32x64), 3-stage cp.async pipeline.
// ---------------------------------------------------------------------------
#define BM 256
#define BN 128
#define BK 64
#define NCHUNK 48
#define STAGE_BYTES 49152              // A 32KB + B 16KB
#define A_OFF(s) ((s) * STAGE_BYTES)
#define B_OFF(s) ((s) * STAGE_BYTES + 32768)
#define GEMM_SMEM (3 * STAGE_BYTES)    // 144 KB

__device__ __forceinline__ void load_chunk(uint32_t sb, int tid, int by, int bx, int c, int s)
{
    int seg  = c >> 4;           // 0: hi*hi, 1: hi*lo, 2: lo*hi
    int koff = (c & 15) * BK;
    const __nv_bfloat16* A = (seg == 2 ? g_xl : g_xh) + (size_t)(by * BM) * K_TOT + koff;
    const __nv_bfloat16* B = (seg == 1 ? g_wtl : g_wth) + (size_t)(bx * BN) * K_TOT + koff;
    uint32_t ab = sb + A_OFF(s), bb = sb + B_OFF(s);
#pragma unroll
    for (int i = 0; i < 4; i++) {            // A: 256 rows x 8 chunks = 2048 slots
        int slot = i * 512 + tid;
        int r   = slot >> 3;
        int c16 = slot & 7;
        uint32_t off = (uint32_t)(r * 128 + ((c16 ^ (r & 7)) * 16));
        cp16(ab + off, A + (size_t)r * K_TOT + c16 * 8);
    }
#pragma unroll
    for (int i = 0; i < 2; i++) {            // B: 128 rows x 8 chunks = 1024 slots
        int slot = i * 512 + tid;
        int r   = slot >> 3;
        int c16 = slot & 7;
        uint32_t off = (uint32_t)(r * 128 + ((c16 ^ (r & 7)) * 16));
        cp16(bb + off, B + (size_t)r * K_TOT + c16 * 8);
    }
}

__global__ __launch_bounds__(512, 1) void qkv_mma_kernel(const float* __restrict__ bias)
{
    extern __shared__ __align__(128) uint8_t smem[];
    uint32_t sb = smem_u32(smem);
    const int tid  = threadIdx.x;
    const int wid  = tid >> 5;
    const int lane = tid & 31;
    const int bx = blockIdx.x;    // N tile 0..23
    const int by = blockIdx.y;    // M tile 0..127
    const int wm = wid >> 1;      // 0..7  (M dir)
    const int wn = wid & 1;       // 0..1  (N dir)

    float acc[2][8][4];
#pragma unroll
    for (int mt = 0; mt < 2; mt++)
#pragma unroll
        for (int nt = 0; nt < 8; nt++)
#pragma unroll
            for (int j = 0; j < 4; j++) acc[mt][nt][j] = 0.f;

    load_chunk(sb, tid, by, bx, 0, 0); cp_commit();
    load_chunk(sb, tid, by, bx, 1, 1); cp_commit();

    const int a_r = wm * 32 + (lane & 15);                      // + mt*16
    const int a_h = lane >> 4;
    const int b_r = wn * 64 + ((lane >> 4) << 3) + (lane & 7);  // + np*16
    const int b_h = (lane >> 3) & 1;

    for (int ch = 0; ch < NCHUNK; ch++) {
        const int s = ch % 3;
        asm volatile("cp.async.wait_group 1;" ::: "memory");
        __syncthreads();
        if (ch + 2 < NCHUNK) load_chunk(sb, tid, by, bx, ch + 2, (ch + 2) % 3);
        cp_commit();

        const uint32_t abase = sb + A_OFF(s);
        const uint32_t bbase = sb + B_OFF(s);
#pragma unroll
        for (int ks = 0; ks < 4; ks++) {
            uint32_t a[2][4];
#pragma unroll
            for (int mt = 0; mt < 2; mt++) {
                int r   = a_r + mt * 16;
                int c16 = ks * 2 + a_h;
                ldsm4(a[mt], abase + r * 128 + ((c16 ^ (r & 7)) * 16));
            }
            uint32_t b[8][2];
#pragma unroll
            for (int np = 0; np < 4; np++) {
                int r   = b_r + np * 16;
                int c16 = ks * 2 + b_h;
                uint32_t q[4];
                ldsm4(q, bbase + r * 128 + ((c16 ^ (r & 7)) * 16));
                b[np * 2 + 0][0] = q[0]; b[np * 2 + 0][1] = q[1];
                b[np * 2 + 1][0] = q[2]; b[np * 2 + 1][1] = q[3];
            }
#pragma unroll
            for (int mt = 0; mt < 2; mt++)
#pragma unroll
                for (int nt = 0; nt < 8; nt++)
                    mma16816(acc[mt][nt], a[mt], b[nt]);
        }
    }
    asm volatile("cp.async.wait_group 0;" ::: "memory");

    const int ncol0 = bx * BN + wn * 64 + (lane & 3) * 2;
    float b0[8], b1[8];
#pragma unroll
    for (int nt = 0; nt < 8; nt++) {
        b0[nt] = __ldg(bias + ncol0 + nt * 8);
        b1[nt] = __ldg(bias + ncol0 + nt * 8 + 1);
    }
#pragma unroll
    for (int mt = 0; mt < 2; mt++)
#pragma unroll
        for (int half = 0; half < 2; half++) {
            int m = by * BM + wm * 32 + mt * 16 + (lane >> 2) + half * 8;
            float* row = g_qkv + (size_t)m * N_TOT + ncol0;
#pragma unroll
            for (int nt = 0; nt < 8; nt++) {
                float2 v;
                v.x = acc[mt][nt][half * 2 + 0] + b0[nt];
                v.y = acc[mt][nt][half * 2 + 1] + b1[nt];
                *(float2*)(row + nt * 8) = v;
            }
        }
}

// ---------------------------------------------------------------------------
// K2a: partial S over a 512-row n-chunk.  grid (8, 128).
// S_part[d,e] = sum_{n in chunk} q[n,d]*k[n,e]   (unscaled)
// ---------------------------------------------------------------------------
__global__ __launch_bounds__(256) void attn_part_kernel()
{
    __shared__ float pool[2 * 64 * 64];
    float* qs = pool;
    float* ks = pool + 4096;

    const int tid   = threadIdx.x;
    const int chunk = blockIdx.x;        // 0..7
    const int bh    = blockIdx.y;        // 0..127
    const int b     = bh >> 4, h = bh & 15;

    const float* qb = g_qkv + (size_t)b * SEQ * N_TOT + h * 64;
    const float* kb = qb + D_HID;

    const int grp = tid >> 6;
    const int s   = tid & 63;
    const int d0  = (s >> 2) * 4;
    const int e0  = (s & 3) * 16;

    unsigned long long acc2[4][8];
#pragma unroll
    for (int i = 0; i < 4; i++)
#pragma unroll
        for (int j = 0; j < 8; j++) acc2[i][j] = 0ull;

    for (int c = 0; c < 8; c++) {
        const int n0 = chunk * 512 + c * 64;
#pragma unroll
        for (int i = 0; i < 4; i++) {
            int idx = i * 256 + tid;
            int row = idx >> 4;
            int c4  = idx & 15;
            *(float4*)(qs + row * 64 + c4 * 4) =
                *(const float4*)(qb + (size_t)(n0 + row) * N_TOT + c4 * 4);
            *(float4*)(ks + row * 64 + c4 * 4) =
                *(const float4*)(kb + (size_t)(n0 + row) * N_TOT + c4 * 4);
        }
        __syncthreads();

        const int nbase = grp * 16;
#pragma unroll 4
        for (int nn = 0; nn < 16; nn++) {
            const int n = nbase + nn;
            float4 qv = *(const float4*)(qs + n * 64 + d0);
            unsigned long long qp[4];
            PACK2(qp[0], qv.x, qv.x);
            PACK2(qp[1], qv.y, qv.y);
            PACK2(qp[2], qv.z, qv.z);
            PACK2(qp[3], qv.w, qv.w);
#pragma unroll
            for (int j4 = 0; j4 < 4; j4++) {
                double2 kd = *(const double2*)(ks + n * 64 + e0 + j4 * 4);
                unsigned long long k0 = __double_as_longlong(kd.x);
                unsigned long long k1 = __double_as_longlong(kd.y);
#pragma unroll
                for (int i = 0; i < 4; i++) {
                    FMA2(acc2[i][j4 * 2 + 0], qp[i], k0);
                    FMA2(acc2[i][j4 * 2 + 1], qp[i], k1);
                }
            }
        }
        __syncthreads();
    }

    // group reduce into padded S, then write partial
    float* S = pool;                       // [64][68]
    const float* af = (const float*)acc2;  // 64 floats: [i][jj] = af[i*16+jj]
    for (int g = 0; g < 4; g++) {
        if (grp == g) {
#pragma unroll
            for (int i = 0; i < 4; i++)
#pragma unroll
                for (int jj = 0; jj < 16; jj++) {
                    float v = af[i * 16 + jj];
                    if (g == 0) S[(d0 + i) * 68 + e0 + jj]  = v;
                    else        S[(d0 + i) * 68 + e0 + jj] += v;
                }
        }
        __syncthreads();
    }

    float* pg = g_part + ((size_t)chunk * 128 + bh) * 4096;
#pragma unroll
    for (int i = 0; i < 16; i++) {
        int flat = i * 256 + tid;
        int d = flat >> 6, e = flat & 63;
        pg[flat] = S[d * 68 + e];
    }
}

// ---------------------------------------------------------------------------
// K2b: reduce 8 partials, scale, softmax over e.  grid 128.
// ---------------------------------------------------------------------------
__global__ __launch_bounds__(256) void attn_softmax_kernel()
{
    __shared__ float S[64 * 68 + 128];
    float* mrow = S + 64 * 68;
    float* irow = mrow + 64;

    const int tid = threadIdx.x;
    const int bh  = blockIdx.x;

#pragma unroll
    for (int i = 0; i < 16; i++) {
        int flat = i * 256 + tid;
        float v = 0.f;
#pragma unroll
        for (int c = 0; c < 8; c++)
            v += g_part[((size_t)c * 128 + bh) * 4096 + flat];
        int d = flat >> 6, e = flat & 63;
        S[d * 68 + e] = v * 0.125f;
    }
    __syncthreads();

    if (tid < 64) {
        float m = -3.4e38f;
#pragma unroll
        for (int e = 0; e < 64; e++) m = fmaxf(m, S[tid * 68 + e]);
        float sum = 0.f;
#pragma unroll
        for (int e = 0; e < 64; e++) sum += __expf(S[tid * 68 + e] - m);
        mrow[tid] = m;
        irow[tid] = 1.f / sum;
    }
    __syncthreads();

    float* ag = g_attn + (size_t)bh * 4096;
#pragma unroll
    for (int i = 0; i < 16; i++) {
        int flat = i * 256 + tid;
        int d = flat >> 6, e = flat & 63;
        ag[flat] = __expf(S[d * 68 + e] - mrow[d]) * irow[d];
    }
}

// ---------------------------------------------------------------------------
// K3: out[n,e] = sum_d v[n,d] * attn[d,e].  grid (16, 128), thread = 1 n-row.
// attn broadcast from smem, f32x2 inner, double-buffered v loads.
// ---------------------------------------------------------------------------
__global__ __launch_bounds__(256) void out_gemm_kernel(float* __restrict__ out)
{
    __shared__ float at[64 * 64];

    const int tid = threadIdx.x;
    const int bh  = blockIdx.y;
    const int b   = bh >> 4, h = bh & 15;
    const int n   = blockIdx.x * 256 + tid;

    const float* ag = g_attn + (size_t)bh * 4096;
#pragma unroll
    for (int i = 0; i < 4; i++) {
        int idx = i * 256 + tid;
        *(float4*)(at + idx * 4) = *(const float4*)(ag + idx * 4);
    }
    __syncthreads();

    const float* vrow = g_qkv + ((size_t)b * SEQ + n) * N_TOT + 2 * D_HID + h * 64;

    unsigned long long acc2[32];
#pragma unroll
    for (int j = 0; j < 32; j++) acc2[j] = 0ull;

    float4 vb0[2], vb1[2];
    vb0[0] = *(const float4*)(vrow + 0);
    vb0[1] = *(const float4*)(vrow + 4);

    for (int d8 = 0; d8 < 8; d8++) {
        if (d8 + 1 < 8) {
            vb1[0] = *(const float4*)(vrow + (d8 + 1) * 8 + 0);
            vb1[1] = *(const float4*)(vrow + (d8 + 1) * 8 + 4);
        }
        float vv[8] = {vb0[0].x, vb0[0].y, vb0[0].z, vb0[0].w,
                       vb0[1].x, vb0[1].y, vb0[1].z, vb0[1].w};
#pragma unroll
        for (int dd = 0; dd < 8; dd++) {
            const int d = d8 * 8 + dd;
            unsigned long long vp;
            PACK2(vp, vv[dd], vv[dd]);
            const double2* ar = (const double2*)(at + d * 64);
#pragma unroll
            for (int j8 = 0; j8 < 16; j8++) {
                double2 t = ar[j8];
                unsigned long long a0 = __double_as_longlong(t.x);
                unsigned long long a1 = __double_as_longlong(t.y);
                FMA2(acc2[j8 * 2 + 0], vp, a0);
                FMA2(acc2[j8 * 2 + 1], vp, a1);
            }
        }
        vb0[0] = vb1[0]; vb0[1] = vb1[1];
    }

    const float* af = (const float*)acc2;   // 64 floats, e-ordered
    float* orow = out + ((size_t)b * SEQ + n) * D_HID + h * 64;
#pragma unroll
    for (int j = 0; j < 16; j++)
        *(float4*)(orow + j * 4) = *(const float4*)(af + j * 4);
}

// ---------------------------------------------------------------------------
extern "C" void kernel_launch(void* const* d_in, const int* in_sizes, int n_in,
                              void* d_out, int out_size)
{
    const float* x    = (const float*)d_in[0];
    const float* W    = (const float*)d_in[1];
    const float* bias = (const float*)d_in[2];
    float* out = (float*)d_out;

    convert_x_kernel<<<(M_TOT * K_TOT) / (256 * 8), 256>>>(x);
    convert_w_kernel<<<dim3(N_TOT / 32, K_TOT / 32), dim3(32, 8)>>>(W);

    cudaFuncSetAttribute(qkv_mma_kernel, cudaFuncAttributeMaxDynamicSharedMemorySize, GEMM_SMEM);
    qkv_mma_kernel<<<dim3(N_TOT / BN, M_TOT / BM), 512, GEMM_SMEM>>>(bias);

    attn_part_kernel<<<dim3(8, BATCH * N_HEADS), 256>>>();
    attn_softmax_kernel<<<BATCH * N_HEADS, 256>>>();

    out_gemm_kernel<<<dim3(SEQ / 256, BATCH * N_HEADS), 256>>>(out);
}

// round 5
// speedup vs baseline: 2.9132x; 1.1782x over previous
#include <cuda_runtime.h>
#include <cuda_bf16.h>
#include <cstdint>

#define BATCH   8
#define SEQ     4096
#define D_HID   1024
#define N_HEADS 16
#define D_HEAD  64
#define M_TOT   (BATCH * SEQ)     // 32768
#define N_TOT   (3 * D_HID)       // 3072
#define K_TOT   (D_HID)           // 1024

// Scratch (allocation-free rule: __device__ globals)
__device__ float g_qkv[(size_t)M_TOT * N_TOT];
__device__ float g_part[(size_t)8 * 128 * 4096];
__device__ __nv_bfloat16 g_ath[(size_t)128 * 4096];   // attn^T [bh][e][d] hi
__device__ __nv_bfloat16 g_atl[(size_t)128 * 4096];   // attn^T lo
__device__ __nv_bfloat16 g_xh[(size_t)M_TOT * K_TOT];
__device__ __nv_bfloat16 g_xl[(size_t)M_TOT * K_TOT];
__device__ __nv_bfloat16 g_wth[(size_t)N_TOT * K_TOT];
__device__ __nv_bfloat16 g_wtl[(size_t)N_TOT * K_TOT];

// ---------------------------------------------------------------------------
// helpers
// ---------------------------------------------------------------------------
__device__ __forceinline__ uint32_t smem_u32(const void* p) {
    uint32_t a;
    asm("{ .reg .u64 t; cvta.to.shared.u64 t, %1; cvt.u32.u64 %0, t; }" : "=r"(a) : "l"(p));
    return a;
}
__device__ __forceinline__ void cp16(uint32_t smem_dst, const void* gsrc) {
    asm volatile("cp.async.cg.shared.global [%0], [%1], 16;" :: "r"(smem_dst), "l"(gsrc));
}
__device__ __forceinline__ void cp_commit() {
    asm volatile("cp.async.commit_group;" ::: "memory");
}
__device__ __forceinline__ void ldsm4(uint32_t* r, uint32_t addr) {
    asm volatile("ldmatrix.sync.aligned.m8n8.x4.shared.b16 {%0,%1,%2,%3}, [%4];"
                 : "=r"(r[0]), "=r"(r[1]), "=r"(r[2]), "=r"(r[3]) : "r"(addr));
}
__device__ __forceinline__ void mma16816(float* c, const uint32_t* a, const uint32_t* b) {
    asm volatile("mma.sync.aligned.m16n8k16.row.col.f32.bf16.bf16.f32 "
                 "{%0,%1,%2,%3}, {%4,%5,%6,%7}, {%8,%9}, {%0,%1,%2,%3};"
                 : "+f"(c[0]), "+f"(c[1]), "+f"(c[2]), "+f"(c[3])
                 : "r"(a[0]), "r"(a[1]), "r"(a[2]), "r"(a[3]), "r"(b[0]), "r"(b[1]));
}
__device__ __forceinline__ uint32_t pack_bf16(float x, float y) {
    __nv_bfloat162 t = __floats2bfloat162_rn(x, y);
    return *reinterpret_cast<uint32_t*>(&t);
}

// ---------------------------------------------------------------------------
// Conversion kernels (fp32 -> bf16 hi/lo split)
// ---------------------------------------------------------------------------
__global__ __launch_bounds__(256) void convert_x_kernel(const float* __restrict__ x)
{
    size_t i = ((size_t)blockIdx.x * 256 + threadIdx.x) * 8;
    float4 a = *(const float4*)(x + i);
    float4 b = *(const float4*)(x + i + 4);
    float v[8] = {a.x, a.y, a.z, a.w, b.x, b.y, b.z, b.w};
    __nv_bfloat16 hi[8], lo[8];
#pragma unroll
    for (int j = 0; j < 8; j++) {
        hi[j] = __float2bfloat16(v[j]);
        lo[j] = __float2bfloat16(v[j] - __bfloat162float(hi[j]));
    }
    *(uint4*)(g_xh + i) = *(uint4*)hi;
    *(uint4*)(g_xl + i) = *(uint4*)lo;
}

__global__ __launch_bounds__(256) void convert_w_kernel(const float* __restrict__ W)
{
    __shared__ float t[32][33];
    int x0 = blockIdx.x * 32;
    int y0 = blockIdx.y * 32;
    int tx = threadIdx.x, ty = threadIdx.y;
#pragma unroll
    for (int j = 0; j < 4; j++)
        t[ty + j * 8][tx] = W[(size_t)(y0 + ty + j * 8) * N_TOT + x0 + tx];
    __syncthreads();
#pragma unroll
    for (int j = 0; j < 4; j++) {
        int n = x0 + ty + j * 8;
        int k = y0 + tx;
        float v = t[tx][ty + j * 8];
        __nv_bfloat16 hi = __float2bfloat16(v);
        __nv_bfloat16 lo = __float2bfloat16(v - __bfloat162float(hi));
        g_wth[(size_t)n * K_TOT + k] = hi;
        g_wtl[(size_t)n * K_TOT + k] = lo;
    }
}

// ---------------------------------------------------------------------------
// K1: qkv = x @ W + b, mma.sync bf16 3-term split. 256x128, BK=64, 4 stages.
// ---------------------------------------------------------------------------
#define BM 256
#define BN 128
#define BK 64
#define NCHUNK 48
#define STAGE_BYTES 49152
#define A_OFF(s) ((s) * STAGE_BYTES)
#define B_OFF(s) ((s) * STAGE_BYTES + 32768)
#define GEMM_SMEM (4 * STAGE_BYTES)    // 192 KB

__device__ __forceinline__ void load_chunk(uint32_t sb, int tid, int by, int bx, int c, int s)
{
    int seg  = c >> 4;
    int koff = (c & 15) * BK;
    const __nv_bfloat16* A = (seg == 2 ? g_xl : g_xh) + (size_t)(by * BM) * K_TOT + koff;
    const __nv_bfloat16* B = (seg == 1 ? g_wtl : g_wth) + (size_t)(bx * BN) * K_TOT + koff;
    uint32_t ab = sb + A_OFF(s), bb = sb + B_OFF(s);
#pragma unroll
    for (int i = 0; i < 4; i++) {
        int slot = i * 512 + tid;
        int r   = slot >> 3;
        int c16 = slot & 7;
        uint32_t off = (uint32_t)(r * 128 + ((c16 ^ (r & 7)) * 16));
        cp16(ab + off, A + (size_t)r * K_TOT + c16 * 8);
    }
#pragma unroll
    for (int i = 0; i < 2; i++) {
        int slot = i * 512 + tid;
        int r   = slot >> 3;
        int c16 = slot & 7;
        uint32_t off = (uint32_t)(r * 128 + ((c16 ^ (r & 7)) * 16));
        cp16(bb + off, B + (size_t)r * K_TOT + c16 * 8);
    }
}

__global__ __launch_bounds__(512, 1) void qkv_mma_kernel(const float* __restrict__ bias)
{
    extern __shared__ __align__(128) uint8_t smem[];
    uint32_t sb = smem_u32(smem);
    const int tid  = threadIdx.x;
    const int wid  = tid >> 5;
    const int lane = tid & 31;
    const int bx = blockIdx.x;
    const int by = blockIdx.y;
    const int wm = wid >> 1;
    const int wn = wid & 1;

    float acc[2][8][4];
#pragma unroll
    for (int mt = 0; mt < 2; mt++)
#pragma unroll
        for (int nt = 0; nt < 8; nt++)
#pragma unroll
            for (int j = 0; j < 4; j++) acc[mt][nt][j] = 0.f;

    load_chunk(sb, tid, by, bx, 0, 0); cp_commit();
    load_chunk(sb, tid, by, bx, 1, 1); cp_commit();
    load_chunk(sb, tid, by, bx, 2, 2); cp_commit();

    const int a_r = wm * 32 + (lane & 15);
    const int a_h = lane >> 4;
    const int b_r = wn * 64 + ((lane >> 4) << 3) + (lane & 7);
    const int b_h = (lane >> 3) & 1;

    for (int ch = 0; ch < NCHUNK; ch++) {
        const int s = ch & 3;
        asm volatile("cp.async.wait_group 2;" ::: "memory");
        __syncthreads();
        if (ch + 3 < NCHUNK) load_chunk(sb, tid, by, bx, ch + 3, (ch + 3) & 3);
        cp_commit();

        const uint32_t abase = sb + A_OFF(s);
        const uint32_t bbase = sb + B_OFF(s);
#pragma unroll
        for (int ks = 0; ks < 4; ks++) {
            uint32_t a[2][4];
#pragma unroll
            for (int mt = 0; mt < 2; mt++) {
                int r   = a_r + mt * 16;
                int c16 = ks * 2 + a_h;
                ldsm4(a[mt], abase + r * 128 + ((c16 ^ (r & 7)) * 16));
            }
            uint32_t b[8][2];
#pragma unroll
            for (int np = 0; np < 4; np++) {
                int r   = b_r + np * 16;
                int c16 = ks * 2 + b_h;
                uint32_t q[4];
                ldsm4(q, bbase + r * 128 + ((c16 ^ (r & 7)) * 16));
                b[np * 2 + 0][0] = q[0]; b[np * 2 + 0][1] = q[1];
                b[np * 2 + 1][0] = q[2]; b[np * 2 + 1][1] = q[3];
            }
#pragma unroll
            for (int mt = 0; mt < 2; mt++)
#pragma unroll
                for (int nt = 0; nt < 8; nt++)
                    mma16816(acc[mt][nt], a[mt], b[nt]);
        }
    }
    asm volatile("cp.async.wait_group 0;" ::: "memory");

    const int ncol0 = bx * BN + wn * 64 + (lane & 3) * 2;
    float b0[8], b1[8];
#pragma unroll
    for (int nt = 0; nt < 8; nt++) {
        b0[nt] = __ldg(bias + ncol0 + nt * 8);
        b1[nt] = __ldg(bias + ncol0 + nt * 8 + 1);
    }
#pragma unroll
    for (int mt = 0; mt < 2; mt++)
#pragma unroll
        for (int half = 0; half < 2; half++) {
            int m = by * BM + wm * 32 + mt * 16 + (lane >> 2) + half * 8;
            float* row = g_qkv + (size_t)m * N_TOT + ncol0;
#pragma unroll
            for (int nt = 0; nt < 8; nt++) {
                float2 v;
                v.x = acc[mt][nt][half * 2 + 0] + b0[nt];
                v.y = acc[mt][nt][half * 2 + 1] + b1[nt];
                *(float2*)(row + nt * 8) = v;
            }
        }
}

// ---------------------------------------------------------------------------
// K2a: partial S over a 512-n chunk via tensor cores. grid (8, 128).
// Converts q,k fp32 -> transposed bf16 hi/lo smem planes [64][128n], then
// 3-term mma with K1-style fragments. S_part written fp32 (unscaled).
// smem planes: qh 0 | ql 16K | kh 32K | kl 48K  (rows 256B, 16 chunks, XOR swz)
// ---------------------------------------------------------------------------
#define K2_SMEM 65536

__global__ __launch_bounds__(256) void attn_part_kernel()
{
    extern __shared__ __align__(128) uint8_t smem[];
    uint32_t sb = smem_u32(smem);
    const int tid   = threadIdx.x;
    const int wid   = tid >> 5;
    const int lane  = tid & 31;
    const int chunk = blockIdx.x;        // 0..7
    const int bh    = blockIdx.y;        // 0..127
    const int b     = bh >> 4, h = bh & 15;

    const float* qb = g_qkv + (size_t)b * SEQ * N_TOT + h * 64;
    const float* kb = qb + D_HID;

    // convert-phase mapping: warp covers 8 npairs x 4 d4 (64B contiguous rows)
    const int npl = lane >> 2;           // 0..7
    const int d4l = lane & 3;            // 0..3
    const int npair = wid * 8 + npl;     // 0..63

    // mma-phase mapping: wm 0..1 (32 d), wn 0..3 (16 e)
    const int wm = wid >> 2;
    const int wn = wid & 3;
    const int a_r0 = wm * 32 + (lane & 15);
    const int a_h  = lane >> 4;
    const int b_r0 = wn * 16 + ((lane >> 4) << 3) + (lane & 7);
    const int b_h  = (lane >> 3) & 1;

    float acc[2][2][4];
#pragma unroll
    for (int mt = 0; mt < 2; mt++)
#pragma unroll
        for (int nt = 0; nt < 2; nt++)
#pragma unroll
            for (int j = 0; j < 4; j++) acc[mt][nt][j] = 0.f;

    for (int s = 0; s < 4; s++) {
        if (s) __syncthreads();
        const int n0 = chunk * 512 + s * 128;

        // convert q (planes 0,16K) then k (planes 32K,48K), transposed store
#pragma unroll
        for (int mtx = 0; mtx < 2; mtx++) {
            const float* src = (mtx ? kb : qb) + (size_t)(n0 + npair * 2) * N_TOT;
            uint32_t ph = sb + mtx * 32768;
            uint32_t pl = ph + 16384;
#pragma unroll
            for (int it = 0; it < 4; it++) {
                int d4 = it * 4 + d4l;
                float4 v0 = *(const float4*)(src + d4 * 4);
                float4 v1 = *(const float4*)(src + N_TOT + d4 * 4);
                float a0[4] = {v0.x, v0.y, v0.z, v0.w};
                float a1[4] = {v1.x, v1.y, v1.z, v1.w};
#pragma unroll
                for (int j = 0; j < 4; j++) {
                    int d = d4 * 4 + j;
                    __nv_bfloat16 h0 = __float2bfloat16(a0[j]);
                    __nv_bfloat16 h1 = __float2bfloat16(a1[j]);
                    uint32_t hp = pack_bf16(a0[j], a1[j]);
                    uint32_t lp = pack_bf16(a0[j] - __bfloat162float(h0),
                                            a1[j] - __bfloat162float(h1));
                    uint32_t off = (uint32_t)(d * 256 + (((npair >> 2) ^ (d & 7)) << 4)
                                              + (npair & 3) * 4);
                    *(uint32_t*)(smem + (ph - sb) + off) = hp;
                    *(uint32_t*)(smem + (pl - sb) + off) = lp;
                }
            }
        }
        __syncthreads();

        // mma over K = 128 n (8 k-steps)
#pragma unroll
        for (int ks = 0; ks < 8; ks++) {
            uint32_t aqh[2][4], aql[2][4];
#pragma unroll
            for (int mt = 0; mt < 2; mt++) {
                int r   = a_r0 + mt * 16;
                int c16 = ks * 2 + a_h;
                uint32_t so = (uint32_t)(r * 256 + ((c16 ^ (r & 7)) << 4));
                ldsm4(aqh[mt], sb + so);
                ldsm4(aql[mt], sb + 16384 + so);
            }
            uint32_t bkh[2][2], bkl[2][2];
            {
                int r   = b_r0;
                int c16 = ks * 2 + b_h;
                uint32_t so = (uint32_t)(r * 256 + ((c16 ^ (r & 7)) << 4));
                uint32_t q[4];
                ldsm4(q, sb + 32768 + so);
                bkh[0][0] = q[0]; bkh[0][1] = q[1]; bkh[1][0] = q[2]; bkh[1][1] = q[3];
                ldsm4(q, sb + 49152 + so);
                bkl[0][0] = q[0]; bkl[0][1] = q[1]; bkl[1][0] = q[2]; bkl[1][1] = q[3];
            }
#pragma unroll
            for (int mt = 0; mt < 2; mt++)
#pragma unroll
                for (int nt = 0; nt < 2; nt++) {
                    mma16816(acc[mt][nt], aqh[mt], bkh[nt]);
                    mma16816(acc[mt][nt], aqh[mt], bkl[nt]);
                    mma16816(acc[mt][nt], aql[mt], bkh[nt]);
                }
        }
    }

    // write partial S (fp32, unscaled)
    float* pg = g_part + ((size_t)chunk * 128 + bh) * 4096;
#pragma unroll
    for (int mt = 0; mt < 2; mt++)
#pragma unroll
        for (int nt = 0; nt < 2; nt++)
#pragma unroll
            for (int half = 0; half < 2; half++) {
                int d = wm * 32 + mt * 16 + (lane >> 2) + half * 8;
                int e = wn * 16 + nt * 8 + (lane & 3) * 2;
                float2 v;
                v.x = acc[mt][nt][half * 2 + 0];
                v.y = acc[mt][nt][half * 2 + 1];
                *(float2*)(pg + d * 64 + e) = v;
            }
}

// ---------------------------------------------------------------------------
// K2b: reduce 8 partials, scale, softmax over e; emit attn^T bf16 hi/lo.
// ---------------------------------------------------------------------------
__global__ __launch_bounds__(256) void attn_softmax_kernel()
{
    __shared__ float S[64 * 68 + 128];
    float* mrow = S + 64 * 68;
    float* irow = mrow + 64;

    const int tid = threadIdx.x;
    const int bh  = blockIdx.x;

#pragma unroll
    for (int i = 0; i < 16; i++) {
        int flat = i * 256 + tid;
        float v = 0.f;
#pragma unroll
        for (int c = 0; c < 8; c++)
            v += g_part[((size_t)c * 128 + bh) * 4096 + flat];
        int d = flat >> 6, e = flat & 63;
        S[d * 68 + e] = v * 0.125f;
    }
    __syncthreads();

    if (tid < 64) {
        float m = -3.4e38f;
#pragma unroll
        for (int e = 0; e < 64; e++) m = fmaxf(m, S[tid * 68 + e]);
        float sum = 0.f;
#pragma unroll
        for (int e = 0; e < 64; e++) sum += __expf(S[tid * 68 + e] - m);
        mrow[tid] = m;
        irow[tid] = 1.f / sum;
    }
    __syncthreads();

    __nv_bfloat16* ah = g_ath + (size_t)bh * 4096;
    __nv_bfloat16* al = g_atl + (size_t)bh * 4096;
#pragma unroll
    for (int i = 0; i < 16; i++) {
        int flat = i * 256 + tid;      // flat = e*64 + d  (transposed layout)
        int e = flat >> 6, d = flat & 63;
        float a = __expf(S[d * 68 + e] - mrow[d]) * irow[d];
        __nv_bfloat16 hi = __float2bfloat16(a);
        ah[flat] = hi;
        al[flat] = __float2bfloat16(a - __bfloat162float(hi));
    }
}

// ---------------------------------------------------------------------------
// K3: out[n,e] = sum_d v[n,d] * attn[d,e] via tensor cores.
// Block 128n x 64e, K=64 d. A = v bf16 split (converted in-kernel, d-contig),
// B = attn^T bf16 planes (cp.async, d-contig). grid (32, 128).
// smem: vh 0 | vl 16K | ah 32K | al 40K   (rows 128B, 8 chunks, XOR swz)
// ---------------------------------------------------------------------------
__global__ __launch_bounds__(256) void out_mma_kernel(float* __restrict__ out)
{
    __shared__ __align__(128) uint8_t smem[49152];
    uint32_t sb = smem_u32(smem);
    const int tid  = threadIdx.x;
    const int wid  = tid >> 5;
    const int lane = tid & 31;
    const int bh   = blockIdx.y;
    const int b    = bh >> 4, h = bh & 15;
    const int nt0  = blockIdx.x * 128;

    // attn^T planes via cp.async (swizzled dst)
    const __nv_bfloat16* agh = g_ath + (size_t)bh * 4096;
    const __nv_bfloat16* agl = g_atl + (size_t)bh * 4096;
#pragma unroll
    for (int i = 0; i < 2; i++) {
        int slot = i * 256 + tid;       // 0..511
        int r = slot >> 3, c = slot & 7;
        uint32_t dst = (uint32_t)(r * 128 + ((c ^ (r & 7)) << 4));
        cp16(sb + 32768 + dst, agh + r * 64 + c * 8);
        cp16(sb + 40960 + dst, agl + r * 64 + c * 8);
    }
    cp_commit();

    // v tile load + bf16 split (no transpose needed: stored d-contiguous)
    const float* vb = g_qkv + ((size_t)b * SEQ + nt0) * N_TOT + 2 * D_HID + h * 64;
#pragma unroll
    for (int i = 0; i < 8; i++) {
        int slot = i * 256 + tid;       // 0..2047
        int r = slot >> 4, d4 = slot & 15;
        float4 v = *(const float4*)(vb + (size_t)r * N_TOT + d4 * 4);
        uint2 hp, lp;
        __nv_bfloat16 h0 = __float2bfloat16(v.x), h1 = __float2bfloat16(v.y);
        __nv_bfloat16 h2 = __float2bfloat16(v.z), h3 = __float2bfloat16(v.w);
        hp.x = pack_bf16(v.x, v.y);
        hp.y = pack_bf16(v.z, v.w);
        lp.x = pack_bf16(v.x - __bfloat162float(h0), v.y - __bfloat162float(h1));
        lp.y = pack_bf16(v.z - __bfloat162float(h2), v.w - __bfloat162float(h3));
        uint32_t off = (uint32_t)(r * 128 + (((d4 >> 1) ^ (r & 7)) << 4) + (d4 & 1) * 8);
        *(uint2*)(smem + off)         = hp;
        *(uint2*)(smem + 16384 + off) = lp;
    }
    asm volatile("cp.async.wait_group 0;" ::: "memory");
    __syncthreads();

    // mma: wm 0..3 (32 n), wn 0..1 (32 e)
    const int wm = wid >> 1;
    const int wn = wid & 1;
    const int a_r0 = wm * 32 + (lane & 15);
    const int a_h  = lane >> 4;
    const int b_r0 = wn * 32 + ((lane >> 4) << 3) + (lane & 7);
    const int b_h  = (lane >> 3) & 1;

    float acc[2][4][4];
#pragma unroll
    for (int mt = 0; mt < 2; mt++)
#pragma unroll
        for (int nt = 0; nt < 4; nt++)
#pragma unroll
            for (int j = 0; j < 4; j++) acc[mt][nt][j] = 0.f;

#pragma unroll
    for (int ks = 0; ks < 4; ks++) {
        uint32_t avh[2][4], avl[2][4];
#pragma unroll
        for (int mt = 0; mt < 2; mt++) {
            int r   = a_r0 + mt * 16;
            int c16 = ks * 2 + a_h;
            uint32_t so = (uint32_t)(r * 128 + ((c16 ^ (r & 7)) << 4));
            ldsm4(avh[mt], sb + so);
            ldsm4(avl[mt], sb + 16384 + so);
        }
        uint32_t bah[4][2], bal[4][2];
#pragma unroll
        for (int np = 0; np < 2; np++) {
            int r   = b_r0 + np * 16;
            int c16 = ks * 2 + b_h;
            uint32_t so = (uint32_t)(r * 128 + ((c16 ^ (r & 7)) << 4));
            uint32_t q[4];
            ldsm4(q, sb + 32768 + so);
            bah[np * 2 + 0][0] = q[0]; bah[np * 2 + 0][1] = q[1];
            bah[np * 2 + 1][0] = q[2]; bah[np * 2 + 1][1] = q[3];
            ldsm4(q, sb + 40960 + so);
            bal[np * 2 + 0][0] = q[0]; bal[np * 2 + 0][1] = q[1];
            bal[np * 2 + 1][0] = q[2]; bal[np * 2 + 1][1] = q[3];
        }
#pragma unroll
        for (int mt = 0; mt < 2; mt++)
#pragma unroll
            for (int nt = 0; nt < 4; nt++) {
                mma16816(acc[mt][nt], avh[mt], bah[nt]);
                mma16816(acc[mt][nt], avh[mt], bal[nt]);
                mma16816(acc[mt][nt], avl[mt], bah[nt]);
            }
    }

    // epilogue: fp32 out
#pragma unroll
    for (int mt = 0; mt < 2; mt++)
#pragma unroll
        for (int half = 0; half < 2; half++) {
            int n = nt0 + wm * 32 + mt * 16 + (lane >> 2) + half * 8;
            float* orow = out + ((size_t)b * SEQ + n) * D_HID + h * 64
                          + wn * 32 + (lane & 3) * 2;
#pragma unroll
            for (int nt = 0; nt < 4; nt++) {
                float2 v;
                v.x = acc[mt][nt][half * 2 + 0];
                v.y = acc[mt][nt][half * 2 + 1];
                *(float2*)(orow + nt * 8) = v;
            }
        }
}

// ---------------------------------------------------------------------------
extern "C" void kernel_launch(void* const* d_in, const int* in_sizes, int n_in,
                              void* d_out, int out_size)
{
    const float* x    = (const float*)d_in[0];
    const float* W    = (const float*)d_in[1];
    const float* bias = (const float*)d_in[2];
    float* out = (float*)d_out;

    convert_x_kernel<<<(M_TOT * K_TOT) / (256 * 8), 256>>>(x);
    convert_w_kernel<<<dim3(N_TOT / 32, K_TOT / 32), dim3(32, 8)>>>(W);

    cudaFuncSetAttribute(qkv_mma_kernel, cudaFuncAttributeMaxDynamicSharedMemorySize, GEMM_SMEM);
    qkv_mma_kernel<<<dim3(N_TOT / BN, M_TOT / BM), 512, GEMM_SMEM>>>(bias);

    cudaFuncSetAttribute(attn_part_kernel, cudaFuncAttributeMaxDynamicSharedMemorySize, K2_SMEM);
    attn_part_kernel<<<dim3(8, BATCH * N_HEADS), 256, K2_SMEM>>>();

    attn_softmax_kernel<<<BATCH * N_HEADS, 256>>>();

    out_mma_kernel<<<dim3(SEQ / 128, BATCH * N_HEADS), 256>>>(out);
}